// round 15
// baseline (speedup 1.0000x reference)
#include <cuda_runtime.h>
#include <cuda_fp16.h>
#include <math.h>

// Problem constants
#define NN    50000
#define EE    800000
#define DIN   64
#define HIDD  128
#define DOUTC 64
#define BB    2

// ---------------- scratch (static device globals; no allocation) ----------------
// g_h layout is BATCH-INTERLEAVED per node: 32 chunks of 2*VW halves:
// [b0 feats VW*j..][b1 feats VW*j..]
__device__ __half g_h  [BB * NN * 128];  // projected features (interleaved gather table)
__device__ __half g_x16[BB * NN * 128];  // fp16 GEMM input (converted input / fp16 y)
__device__ __half g_wh [32768];          // W1(8192) | W2(16384) | W3(8192) fp16
__device__ float  g_el [BB * NN * 2];    // per-node attention left  (max 2 heads)
__device__ float  g_er [BB * NN * 2];    // per-node attention right
__device__ int    g_rowptr[NN + 1];      // CSR by dst
__device__ int    g_cursor[NN];          // degree / scatter cursor
__device__ int    g_csrc[EE];            // src per CSR slot
__device__ int    g_work[4];             // work-stealing counters (one per aggregate)

__device__ __forceinline__ unsigned smem_u32(const void* p) {
    return (unsigned)__cvta_generic_to_shared(p);
}

__device__ __forceinline__ float2 h2f(unsigned u) {
    return __half22float2(*reinterpret_cast<const __half2*>(&u));
}

// ---------------- fused prep: convert x + W to fp16, zero counters ----------
__global__ void prep_kernel(const float* __restrict__ in,
                            const float* __restrict__ W1,
                            const float* __restrict__ W2,
                            const float* __restrict__ W3) {
    int i = blockIdx.x * blockDim.x + threadIdx.x;
    if (i < BB * NN * DIN / 4) {
        float4 v = reinterpret_cast<const float4*>(in)[i];
        union { __half2 h[2]; uint2 u; } cv;
        cv.h[0] = __floats2half2_rn(v.x, v.y);
        cv.h[1] = __floats2half2_rn(v.z, v.w);
        reinterpret_cast<uint2*>(g_x16)[i] = cv.u;
    }
    if (i < 32768) {
        if (i < 8192)       g_wh[i] = __float2half_rn(W1[i]);
        else if (i < 24576) g_wh[i] = __float2half_rn(W2[i - 8192]);
        else                g_wh[i] = __float2half_rn(W3[i - 24576]);
    }
    if (i < NN) g_cursor[i] = 0;
    if (i < 4)  g_work[i] = 0;
}

// ---------------- CSR build ----------------
__global__ void hist_kernel(const int* __restrict__ dst) {
    int e = blockIdx.x * blockDim.x + threadIdx.x;
    if (e < EE) atomicAdd(&g_cursor[dst[e]], 1);
}

__global__ void scan_kernel() {
    __shared__ int ss[1024];
    const int t  = threadIdx.x;
    const int CH = (NN + 1023) / 1024;
    const int b  = t * CH;
    const int e  = min(b + CH, NN);
    int s = 0;
    for (int i = b; i < e; i++) s += g_cursor[i];
    ss[t] = s;
    __syncthreads();
    for (int off = 1; off < 1024; off <<= 1) {
        int v = (t >= off) ? ss[t - off] : 0;
        __syncthreads();
        ss[t] += v;
        __syncthreads();
    }
    int run = (t == 0) ? 0 : ss[t - 1];
    for (int i = b; i < e; i++) {
        int d = g_cursor[i];
        g_rowptr[i] = run;
        g_cursor[i] = run;
        run += d;
    }
    if (t == 1023) g_rowptr[NN] = ss[1023];
}

__global__ void scatter_kernel(const int* __restrict__ src, const int* __restrict__ dst) {
    int e = blockIdx.x * blockDim.x + threadIdx.x;
    if (e < EE) {
        int p = atomicAdd(&g_cursor[dst[e]], 1);
        g_csrc[p] = src[e];
    }
}

// ---------------- HMMA (mma.sync m16n8k16) GEMM + attention epilogue ----------
template <int K, int HD, int H>
__global__ __launch_bounds__(128) void mma_gemm_att(
    const __half* __restrict__ xbase,
    const __half* __restrict__ Wh,
    const float* __restrict__ al, const float* __restrict__ ar,
    __half* __restrict__ hbase, float* __restrict__ elbase, float* __restrict__ erbase)
{
    constexpr int KS = 64;
    constexpr int PX = KS + 8;
    constexpr int PW = HD + 8;
    constexpr int NT = HD / 8;
    constexpr int D  = HD / H;
    constexpr int VW = HD / 32;

    __shared__ __align__(16) __half xs[64 * PX];
    __shared__ __align__(16) __half ws[KS * PW];
    __shared__ float sal[HD], sar[HD];

    const int bb = blockIdx.y;
    const __half* x  = xbase + (size_t)bb * NN * K;
    float*        el = elbase + (size_t)bb * NN * H;
    float*        er = erbase + (size_t)bb * NN * H;

    const int tid  = threadIdx.x;
    const int warp = tid >> 5;
    const int lane = tid & 31;
    const int g    = lane >> 2;
    const int t    = lane & 3;
    const int row0 = blockIdx.x * 64;

    for (int i = tid; i < HD; i += 128) { sal[i] = al[i]; sar[i] = ar[i]; }

    float C[NT][4];
    #pragma unroll
    for (int j = 0; j < NT; j++)
        #pragma unroll
        for (int c = 0; c < 4; c++) C[j][c] = 0.f;

    for (int ko = 0; ko < K; ko += KS) {
        for (int idx = tid; idx < 64 * (KS / 8); idx += 128) {
            int r = idx / (KS / 8), j = idx % (KS / 8);
            int grow = min(row0 + r, NN - 1);
            *reinterpret_cast<uint4*>(&xs[r * PX + j * 8]) =
                *reinterpret_cast<const uint4*>(&x[(size_t)grow * K + ko + j * 8]);
        }
        for (int idx = tid; idx < KS * (HD / 8); idx += 128) {
            int r = idx / (HD / 8), j = idx % (HD / 8);
            *reinterpret_cast<uint4*>(&ws[r * PW + j * 8]) =
                *reinterpret_cast<const uint4*>(&Wh[(size_t)(ko + r) * HD + j * 8]);
        }
        __syncthreads();

        #pragma unroll
        for (int kk = 0; kk < KS; kk += 16) {
            unsigned a0, a1, a2, a3;
            {
                int i8  = lane & 7;
                int sel = lane >> 3;
                int arow = warp * 16 + i8 + (sel & 1) * 8;
                int akk  = kk + (sel >> 1) * 8;
                unsigned addr = smem_u32(&xs[arow * PX + akk]);
                asm volatile("ldmatrix.sync.aligned.m8n8.x4.shared.b16 {%0,%1,%2,%3}, [%4];"
                             : "=r"(a0), "=r"(a1), "=r"(a2), "=r"(a3) : "r"(addr));
            }
            #pragma unroll
            for (int j = 0; j < NT; j++) {
                unsigned b0, b1;
                int i8 = lane & 7;
                int s  = (lane >> 3) & 1;
                unsigned baddr = smem_u32(&ws[(kk + s * 8 + i8) * PW + j * 8]);
                asm volatile("ldmatrix.sync.aligned.m8n8.x2.trans.shared.b16 {%0,%1}, [%2];"
                             : "=r"(b0), "=r"(b1) : "r"(baddr));
                asm volatile("mma.sync.aligned.m16n8k16.row.col.f32.f16.f16.f32 "
                             "{%0,%1,%2,%3}, {%4,%5,%6,%7}, {%8,%9}, {%0,%1,%2,%3};"
                             : "+f"(C[j][0]), "+f"(C[j][1]), "+f"(C[j][2]), "+f"(C[j][3])
                             : "r"(a0), "r"(a1), "r"(a2), "r"(a3), "r"(b0), "r"(b1));
            }
        }
        __syncthreads();
    }

    const int row_a = row0 + warp * 16 + g;
    const int row_b = row_a + 8;

    float pelA[H], perA[H], pelB[H], perB[H];
    #pragma unroll
    for (int h = 0; h < H; h++) { pelA[h] = 0.f; perA[h] = 0.f; pelB[h] = 0.f; perB[h] = 0.f; }

    #pragma unroll
    for (int j = 0; j < NT; j++) {
        const int cc = j * 8 + 2 * t;
        const int hh = (j * 8) / D;
        const float a0v = sal[cc], a1v = sal[cc + 1];
        const float r0v = sar[cc], r1v = sar[cc + 1];
        pelA[hh] = fmaf(C[j][0], a0v, fmaf(C[j][1], a1v, pelA[hh]));
        perA[hh] = fmaf(C[j][0], r0v, fmaf(C[j][1], r1v, perA[hh]));
        pelB[hh] = fmaf(C[j][2], a0v, fmaf(C[j][3], a1v, pelB[hh]));
        perB[hh] = fmaf(C[j][2], r0v, fmaf(C[j][3], r1v, perB[hh]));
        const int ioff = (cc / VW) * (2 * VW) + bb * VW + (cc % VW);
        if (row_a < NN) {
            __half2 hv = __floats2half2_rn(C[j][0], C[j][1]);
            *reinterpret_cast<unsigned*>(&hbase[(size_t)row_a * (2 * HD) + ioff]) =
                *reinterpret_cast<unsigned*>(&hv);
        }
        if (row_b < NN) {
            __half2 hv = __floats2half2_rn(C[j][2], C[j][3]);
            *reinterpret_cast<unsigned*>(&hbase[(size_t)row_b * (2 * HD) + ioff]) =
                *reinterpret_cast<unsigned*>(&hv);
        }
    }

    #pragma unroll
    for (int h = 0; h < H; h++) {
        pelA[h] += __shfl_xor_sync(0xffffffffu, pelA[h], 1);
        pelA[h] += __shfl_xor_sync(0xffffffffu, pelA[h], 2);
        perA[h] += __shfl_xor_sync(0xffffffffu, perA[h], 1);
        perA[h] += __shfl_xor_sync(0xffffffffu, perA[h], 2);
        pelB[h] += __shfl_xor_sync(0xffffffffu, pelB[h], 1);
        pelB[h] += __shfl_xor_sync(0xffffffffu, pelB[h], 2);
        perB[h] += __shfl_xor_sync(0xffffffffu, perB[h], 1);
        perB[h] += __shfl_xor_sync(0xffffffffu, perB[h], 2);
    }
    if (t == 0) {
        #pragma unroll
        for (int h = 0; h < H; h++) {
            if (row_a < NN) { el[row_a * H + h] = pelA[h]; er[row_a * H + h] = perA[h]; }
            if (row_b < NN) { el[row_b * H + h] = pelB[h]; er[row_b * H + h] = perB[h]; }
        }
    }
}

// ---------------- persistent warp-cooperative edge-softmax + aggregation -----
// Each warp pops nodes from a global counter (perfect load balance, no
// block-drain quantization). Per 32-edge chunk: ONE coalesced csrc load;
// each lane computes its edge's weights (exp once per edge) and stages
// (idx, w) in smem; inner loop streams independent h-gathers.
template <int HD, int H, bool RELU, typename OT>
__global__ __launch_bounds__(256) void aggregate_kernel(
    const __half* __restrict__ hbase, const float* __restrict__ elbase,
    const float* __restrict__ erbase, const float* __restrict__ bias,
    OT* __restrict__ outbase, size_t outstride, int ctr)
{
    constexpr int VW = HD / 32;
    constexpr int D  = HD / H;

    __shared__ int   sidx[8][32];
    __shared__ float swgt[8][32 * 2 * H];

    const float*  el0 = elbase;
    const float*  el1 = elbase + (size_t)NN * H;
    const float*  er0 = erbase;
    const float*  er1 = erbase + (size_t)NN * H;
    OT*           o0  = outbase;
    OT*           o1  = outbase + outstride;

    const int warp = threadIdx.x >> 5;
    const int lane = threadIdx.x & 31;
    const int c0 = lane * VW;
    const int hl = c0 / D;
    const int loff = lane * (2 * VW);

    float bv[VW];
    #pragma unroll
    for (int j = 0; j < VW; j++) bv[j] = bias[c0 + j];

    while (true) {
        // ---- pop next node ----
        int gw;
        if (lane == 0) gw = atomicAdd(&g_work[ctr], 1);
        gw = __shfl_sync(0xffffffffu, gw, 0);
        if (gw >= NN) break;

        const int s0 = g_rowptr[gw];
        const int s1 = g_rowptr[gw + 1];

        float erA[H], erB[H];
        #pragma unroll
        for (int h = 0; h < H; h++) {
            erA[h] = er0[gw * H + h];
            erB[h] = er1[gw * H + h];
        }

        float acc0[VW], acc1[VW];
        #pragma unroll
        for (int j = 0; j < VW; j++) { acc0[j] = 0.f; acc1[j] = 0.f; }
        float psum0[H], psum1[H];
        #pragma unroll
        for (int h = 0; h < H; h++) { psum0[h] = 0.f; psum1[h] = 0.f; }

        for (int p = s0; p < s1; p += 32) {
            const int n = min(32, s1 - p);
            if (lane < n) {
                const int idx = g_csrc[p + lane];
                sidx[warp][lane] = idx;
                #pragma unroll
                for (int h = 0; h < H; h++) {
                    float v0 = el0[idx * H + h] + erA[h];
                    float v1 = el1[idx * H + h] + erB[h];
                    v0 = (v0 > 0.f) ? v0 : 0.2f * v0;
                    v1 = (v1 > 0.f) ? v1 : 0.2f * v1;
                    const float w0 = __expf(v0);
                    const float w1 = __expf(v1);
                    swgt[warp][lane * 2 * H + h]     = w0;
                    swgt[warp][lane * 2 * H + H + h] = w1;
                    psum0[h] += w0;
                    psum1[h] += w1;
                }
            }
            __syncwarp();
            #pragma unroll 4
            for (int j = 0; j < n; j++) {
                const int sj = sidx[warp][j];
                const float wj0 = swgt[warp][j * 2 * H + hl];
                const float wj1 = swgt[warp][j * 2 * H + H + hl];
                const __half* pA = hbase + (size_t)sj * (2 * HD) + loff;
                if constexpr (VW == 4) {
                    uint4 u = *reinterpret_cast<const uint4*>(pA);
                    float2 a = h2f(u.x), b = h2f(u.y);   // batch0
                    float2 c = h2f(u.z), d = h2f(u.w);   // batch1
                    acc0[0] = fmaf(wj0, a.x, acc0[0]);
                    acc0[1] = fmaf(wj0, a.y, acc0[1]);
                    acc0[2] = fmaf(wj0, b.x, acc0[2]);
                    acc0[3] = fmaf(wj0, b.y, acc0[3]);
                    acc1[0] = fmaf(wj1, c.x, acc1[0]);
                    acc1[1] = fmaf(wj1, c.y, acc1[1]);
                    acc1[2] = fmaf(wj1, d.x, acc1[2]);
                    acc1[3] = fmaf(wj1, d.y, acc1[3]);
                } else {
                    uint2 u = *reinterpret_cast<const uint2*>(pA);
                    float2 a = h2f(u.x);                  // batch0
                    float2 c = h2f(u.y);                  // batch1
                    acc0[0] = fmaf(wj0, a.x, acc0[0]);
                    acc0[1] = fmaf(wj0, a.y, acc0[1]);
                    acc1[0] = fmaf(wj1, c.x, acc1[0]);
                    acc1[1] = fmaf(wj1, c.y, acc1[1]);
                }
            }
            __syncwarp();
        }

        #pragma unroll
        for (int h = 0; h < H; h++) {
            #pragma unroll
            for (int off = 16; off > 0; off >>= 1) {
                psum0[h] += __shfl_xor_sync(0xffffffffu, psum0[h], off);
                psum1[h] += __shfl_xor_sync(0xffffffffu, psum1[h], off);
            }
        }
        const float sum0 = psum0[hl];
        const float sum1 = psum1[hl];

        float out0[VW], out1[VW];
        if (s1 > s0) {
            const float i0 = 1.f / sum0;
            const float i1 = 1.f / sum1;
            #pragma unroll
            for (int j = 0; j < VW; j++) {
                out0[j] = fmaf(acc0[j], i0, bv[j]);
                out1[j] = fmaf(acc1[j], i1, bv[j]);
            }
        } else {
            #pragma unroll
            for (int j = 0; j < VW; j++) { out0[j] = bv[j]; out1[j] = bv[j]; }
        }
        if (RELU) {
            #pragma unroll
            for (int j = 0; j < VW; j++) {
                out0[j] = fmaxf(out0[j], 0.f);
                out1[j] = fmaxf(out1[j], 0.f);
            }
        }

        if constexpr (sizeof(OT) == 2) {
            if constexpr (VW == 4) {
                union { __half2 h[2]; uint2 u; } cv0, cv1;
                cv0.h[0] = __floats2half2_rn(out0[0], out0[1]);
                cv0.h[1] = __floats2half2_rn(out0[2], out0[3]);
                cv1.h[0] = __floats2half2_rn(out1[0], out1[1]);
                cv1.h[1] = __floats2half2_rn(out1[2], out1[3]);
                *reinterpret_cast<uint2*>(o0 + (size_t)gw * HD + c0) = cv0.u;
                *reinterpret_cast<uint2*>(o1 + (size_t)gw * HD + c0) = cv1.u;
            } else {
                __half2 v0 = __floats2half2_rn(out0[0], out0[1]);
                __half2 v1 = __floats2half2_rn(out1[0], out1[1]);
                *reinterpret_cast<unsigned*>(o0 + (size_t)gw * HD + c0) =
                    *reinterpret_cast<unsigned*>(&v0);
                *reinterpret_cast<unsigned*>(o1 + (size_t)gw * HD + c0) =
                    *reinterpret_cast<unsigned*>(&v1);
            }
        } else {
            if constexpr (VW == 4) {
                *reinterpret_cast<float4*>(o0 + (size_t)gw * HD + c0) =
                    make_float4(out0[0], out0[1], out0[2], out0[3]);
                *reinterpret_cast<float4*>(o1 + (size_t)gw * HD + c0) =
                    make_float4(out1[0], out1[1], out1[2], out1[3]);
            } else {
                *reinterpret_cast<float2*>(o0 + (size_t)gw * HD + c0) =
                    make_float2(out0[0], out0[1]);
                *reinterpret_cast<float2*>(o1 + (size_t)gw * HD + c0) =
                    make_float2(out1[0], out1[1]);
            }
        }
    }
}

// ---------------- launcher ----------------
extern "C" void kernel_launch(void* const* d_in, const int* in_sizes, int n_in,
                              void* d_out, int out_size)
{
    const float* input = (const float*)d_in[0];
    const int*   src   = (const int*)  d_in[1];
    const int*   dst   = (const int*)  d_in[2];
    const float* W1    = (const float*)d_in[3];
    const float* al1   = (const float*)d_in[4];
    const float* ar1   = (const float*)d_in[5];
    const float* b1    = (const float*)d_in[6];
    const float* W2    = (const float*)d_in[7];
    const float* al2   = (const float*)d_in[8];
    const float* ar2   = (const float*)d_in[9];
    const float* b2    = (const float*)d_in[10];
    const float* W3    = (const float*)d_in[11];
    const float* al3   = (const float*)d_in[12];
    const float* ar3   = (const float*)d_in[13];
    const float* b3    = (const float*)d_in[14];
    float* out = (float*)d_out;

    void *ph, *px, *pw, *pel, *per;
    cudaGetSymbolAddress(&ph,  g_h);
    cudaGetSymbolAddress(&px,  g_x16);
    cudaGetSymbolAddress(&pw,  g_wh);
    cudaGetSymbolAddress(&pel, g_el);
    cudaGetSymbolAddress(&per, g_er);
    __half* hbuf = (__half*)ph;
    __half* x16  = (__half*)px;
    __half* wh   = (__half*)pw;
    float*  elb  = (float*)pel;
    float*  erb  = (float*)per;

    // fused prep (convert + zero) + CSR build
    prep_kernel<<<(BB * NN * DIN / 4 + 255) / 256, 256>>>(input, W1, W2, W3);
    hist_kernel<<<(EE + 255) / 256, 256>>>(dst);
    scan_kernel<<<1, 1024>>>();
    scatter_kernel<<<(EE + 255) / 256, 256>>>(src, dst);

    dim3 ggrid((NN + 63) / 64, BB);
    const int agrid = 592;   // persistent: ~4 blocks/SM on 148 SMs

    // Layer 1: GATConv(64 -> 2 heads x 64)
    mma_gemm_att<64, 128, 2><<<ggrid, 128>>>(x16, wh, al1, ar1, hbuf, elb, erb);
    aggregate_kernel<128, 2, false, __half><<<agrid, 256>>>(hbuf, elb, erb, b1, x16, (size_t)NN * 128, 0);

    // Layer 2: GATConv(128 -> 128, 1 head), ReLU
    mma_gemm_att<128, 128, 1><<<ggrid, 128>>>(x16, wh + 8192, al2, ar2, hbuf, elb, erb);
    aggregate_kernel<128, 1, true, __half><<<agrid, 256>>>(hbuf, elb, erb, b2, x16, (size_t)NN * 128, 1);

    // Layer 3: GATConv(128 -> 64, 1 head)
    mma_gemm_att<128, 64, 1><<<ggrid, 128>>>(x16, wh + 24576, al3, ar3, hbuf, elb, erb);
    aggregate_kernel<64, 1, false, float><<<agrid, 256>>>(hbuf, elb, erb, b3, out, (size_t)NN * DOUTC, 2);
}

// round 16
// speedup vs baseline: 1.1201x; 1.1201x over previous
#include <cuda_runtime.h>
#include <cuda_fp16.h>
#include <math.h>

// Problem constants
#define NN    50000
#define EE    800000
#define DIN   64
#define HIDD  128
#define DOUTC 64
#define BB    2

// ---------------- scratch (static device globals; no allocation) ----------------
// g_h layout is BATCH-INTERLEAVED per node: 32 chunks of 2*VW halves:
// [b0 feats VW*j..][b1 feats VW*j..]
__device__ __half g_h  [BB * NN * 128];  // projected features (interleaved gather table)
__device__ __half g_x16[BB * NN * 128];  // fp16 GEMM input (converted input / fp16 y)
__device__ __half g_wh [32768];          // W1(8192) | W2(16384) | W3(8192) fp16
__device__ float  g_el [BB * NN * 2];    // per-node attention left  (max 2 heads)
__device__ float  g_er [BB * NN * 2];    // per-node attention right
__device__ int    g_rowptr[NN + 1];      // CSR by dst
__device__ int    g_cursor[NN];          // degree / scatter cursor
__device__ int    g_csrc[EE];            // src per CSR slot

__device__ __forceinline__ unsigned smem_u32(const void* p) {
    return (unsigned)__cvta_generic_to_shared(p);
}

__device__ __forceinline__ float2 h2f(unsigned u) {
    return __half22float2(*reinterpret_cast<const __half2*>(&u));
}

// ---------------- fused prep: convert x + W to fp16, zero degree counters ----
__global__ void prep_kernel(const float* __restrict__ in,
                            const float* __restrict__ W1,
                            const float* __restrict__ W2,
                            const float* __restrict__ W3) {
    int i = blockIdx.x * blockDim.x + threadIdx.x;
    if (i < BB * NN * DIN / 4) {
        float4 v = reinterpret_cast<const float4*>(in)[i];
        union { __half2 h[2]; uint2 u; } cv;
        cv.h[0] = __floats2half2_rn(v.x, v.y);
        cv.h[1] = __floats2half2_rn(v.z, v.w);
        reinterpret_cast<uint2*>(g_x16)[i] = cv.u;
    }
    if (i < 32768) {
        if (i < 8192)       g_wh[i] = __float2half_rn(W1[i]);
        else if (i < 24576) g_wh[i] = __float2half_rn(W2[i - 8192]);
        else                g_wh[i] = __float2half_rn(W3[i - 24576]);
    }
    if (i < NN) g_cursor[i] = 0;
}

// ---------------- CSR build ----------------
__global__ void hist_kernel(const int* __restrict__ dst) {
    int e = blockIdx.x * blockDim.x + threadIdx.x;
    if (e < EE) atomicAdd(&g_cursor[dst[e]], 1);
}

__global__ void scan_kernel() {
    __shared__ int ss[1024];
    const int t  = threadIdx.x;
    const int CH = (NN + 1023) / 1024;
    const int b  = t * CH;
    const int e  = min(b + CH, NN);
    int s = 0;
    for (int i = b; i < e; i++) s += g_cursor[i];
    ss[t] = s;
    __syncthreads();
    for (int off = 1; off < 1024; off <<= 1) {
        int v = (t >= off) ? ss[t - off] : 0;
        __syncthreads();
        ss[t] += v;
        __syncthreads();
    }
    int run = (t == 0) ? 0 : ss[t - 1];
    for (int i = b; i < e; i++) {
        int d = g_cursor[i];
        g_rowptr[i] = run;
        g_cursor[i] = run;
        run += d;
    }
    if (t == 1023) g_rowptr[NN] = ss[1023];
}

__global__ void scatter_kernel(const int* __restrict__ src, const int* __restrict__ dst) {
    int e = blockIdx.x * blockDim.x + threadIdx.x;
    if (e < EE) {
        int p = atomicAdd(&g_cursor[dst[e]], 1);
        g_csrc[p] = src[e];
    }
}

// ---------------- HMMA (mma.sync m16n8k16) GEMM + attention epilogue ----------
template <int K, int HD, int H>
__global__ __launch_bounds__(128) void mma_gemm_att(
    const __half* __restrict__ xbase,
    const __half* __restrict__ Wh,
    const float* __restrict__ al, const float* __restrict__ ar,
    __half* __restrict__ hbase, float* __restrict__ elbase, float* __restrict__ erbase)
{
    constexpr int KS = 64;
    constexpr int PX = KS + 8;
    constexpr int PW = HD + 8;
    constexpr int NT = HD / 8;
    constexpr int D  = HD / H;
    constexpr int VW = HD / 32;

    __shared__ __align__(16) __half xs[64 * PX];
    __shared__ __align__(16) __half ws[KS * PW];
    __shared__ float sal[HD], sar[HD];

    const int bb = blockIdx.y;
    const __half* x  = xbase + (size_t)bb * NN * K;
    float*        el = elbase + (size_t)bb * NN * H;
    float*        er = erbase + (size_t)bb * NN * H;

    const int tid  = threadIdx.x;
    const int warp = tid >> 5;
    const int lane = tid & 31;
    const int g    = lane >> 2;
    const int t    = lane & 3;
    const int row0 = blockIdx.x * 64;

    for (int i = tid; i < HD; i += 128) { sal[i] = al[i]; sar[i] = ar[i]; }

    float C[NT][4];
    #pragma unroll
    for (int j = 0; j < NT; j++)
        #pragma unroll
        for (int c = 0; c < 4; c++) C[j][c] = 0.f;

    for (int ko = 0; ko < K; ko += KS) {
        for (int idx = tid; idx < 64 * (KS / 8); idx += 128) {
            int r = idx / (KS / 8), j = idx % (KS / 8);
            int grow = min(row0 + r, NN - 1);
            *reinterpret_cast<uint4*>(&xs[r * PX + j * 8]) =
                *reinterpret_cast<const uint4*>(&x[(size_t)grow * K + ko + j * 8]);
        }
        for (int idx = tid; idx < KS * (HD / 8); idx += 128) {
            int r = idx / (HD / 8), j = idx % (HD / 8);
            *reinterpret_cast<uint4*>(&ws[r * PW + j * 8]) =
                *reinterpret_cast<const uint4*>(&Wh[(size_t)(ko + r) * HD + j * 8]);
        }
        __syncthreads();

        #pragma unroll
        for (int kk = 0; kk < KS; kk += 16) {
            unsigned a0, a1, a2, a3;
            {
                int i8  = lane & 7;
                int sel = lane >> 3;
                int arow = warp * 16 + i8 + (sel & 1) * 8;
                int akk  = kk + (sel >> 1) * 8;
                unsigned addr = smem_u32(&xs[arow * PX + akk]);
                asm volatile("ldmatrix.sync.aligned.m8n8.x4.shared.b16 {%0,%1,%2,%3}, [%4];"
                             : "=r"(a0), "=r"(a1), "=r"(a2), "=r"(a3) : "r"(addr));
            }
            #pragma unroll
            for (int j = 0; j < NT; j++) {
                unsigned b0, b1;
                int i8 = lane & 7;
                int s  = (lane >> 3) & 1;
                unsigned baddr = smem_u32(&ws[(kk + s * 8 + i8) * PW + j * 8]);
                asm volatile("ldmatrix.sync.aligned.m8n8.x2.trans.shared.b16 {%0,%1}, [%2];"
                             : "=r"(b0), "=r"(b1) : "r"(baddr));
                asm volatile("mma.sync.aligned.m16n8k16.row.col.f32.f16.f16.f32 "
                             "{%0,%1,%2,%3}, {%4,%5,%6,%7}, {%8,%9}, {%0,%1,%2,%3};"
                             : "+f"(C[j][0]), "+f"(C[j][1]), "+f"(C[j][2]), "+f"(C[j][3])
                             : "r"(a0), "r"(a1), "r"(a2), "r"(a3), "r"(b0), "r"(b1));
            }
        }
        __syncthreads();
    }

    const int row_a = row0 + warp * 16 + g;
    const int row_b = row_a + 8;

    float pelA[H], perA[H], pelB[H], perB[H];
    #pragma unroll
    for (int h = 0; h < H; h++) { pelA[h] = 0.f; perA[h] = 0.f; pelB[h] = 0.f; perB[h] = 0.f; }

    #pragma unroll
    for (int j = 0; j < NT; j++) {
        const int cc = j * 8 + 2 * t;
        const int hh = (j * 8) / D;
        const float a0v = sal[cc], a1v = sal[cc + 1];
        const float r0v = sar[cc], r1v = sar[cc + 1];
        pelA[hh] = fmaf(C[j][0], a0v, fmaf(C[j][1], a1v, pelA[hh]));
        perA[hh] = fmaf(C[j][0], r0v, fmaf(C[j][1], r1v, perA[hh]));
        pelB[hh] = fmaf(C[j][2], a0v, fmaf(C[j][3], a1v, pelB[hh]));
        perB[hh] = fmaf(C[j][2], r0v, fmaf(C[j][3], r1v, perB[hh]));
        const int ioff = (cc / VW) * (2 * VW) + bb * VW + (cc % VW);
        if (row_a < NN) {
            __half2 hv = __floats2half2_rn(C[j][0], C[j][1]);
            *reinterpret_cast<unsigned*>(&hbase[(size_t)row_a * (2 * HD) + ioff]) =
                *reinterpret_cast<unsigned*>(&hv);
        }
        if (row_b < NN) {
            __half2 hv = __floats2half2_rn(C[j][2], C[j][3]);
            *reinterpret_cast<unsigned*>(&hbase[(size_t)row_b * (2 * HD) + ioff]) =
                *reinterpret_cast<unsigned*>(&hv);
        }
    }

    #pragma unroll
    for (int h = 0; h < H; h++) {
        pelA[h] += __shfl_xor_sync(0xffffffffu, pelA[h], 1);
        pelA[h] += __shfl_xor_sync(0xffffffffu, pelA[h], 2);
        perA[h] += __shfl_xor_sync(0xffffffffu, perA[h], 1);
        perA[h] += __shfl_xor_sync(0xffffffffu, perA[h], 2);
        pelB[h] += __shfl_xor_sync(0xffffffffu, pelB[h], 1);
        pelB[h] += __shfl_xor_sync(0xffffffffu, pelB[h], 2);
        perB[h] += __shfl_xor_sync(0xffffffffu, perB[h], 1);
        perB[h] += __shfl_xor_sync(0xffffffffu, perB[h], 2);
    }
    if (t == 0) {
        #pragma unroll
        for (int h = 0; h < H; h++) {
            if (row_a < NN) { el[row_a * H + h] = pelA[h]; er[row_a * H + h] = perA[h]; }
            if (row_b < NN) { el[row_b * H + h] = pelB[h]; er[row_b * H + h] = perB[h]; }
        }
    }
}

// ---------------- node-pipelined warp-cooperative aggregation ----------------
// Each warp owns 4 consecutive nodes with double-buffered staging: while
// streaming node i's h-gathers, node i+1's prep loads (rowptr/csrc/el/exp)
// are already in flight into the other buffer. Softmax denominators are
// accumulated redundantly per lane during the stream (no warp reduction).
template <int HD, int H, bool RELU, typename OT>
__global__ __launch_bounds__(256) void aggregate_kernel(
    const __half* __restrict__ hbase, const float* __restrict__ elbase,
    const float* __restrict__ erbase, const float* __restrict__ bias,
    OT* __restrict__ outbase, size_t outstride)
{
    constexpr int VW  = HD / 32;
    constexpr int D   = HD / H;
    constexpr int NPW = 4;          // nodes per warp (NN % 4 == 0)

    __shared__ int   sidx[8][2][32];
    __shared__ float swgt[8][2][32 * 2 * H];

    const float*  el0 = elbase;
    const float*  el1 = elbase + (size_t)NN * H;
    const float*  er0 = erbase;
    const float*  er1 = erbase + (size_t)NN * H;
    OT*           o0  = outbase;
    OT*           o1  = outbase + outstride;

    const int warp  = threadIdx.x >> 5;
    const int lane  = threadIdx.x & 31;
    const int gw    = (blockIdx.x * blockDim.x + threadIdx.x) >> 5;
    const int nbase = gw * NPW;
    if (nbase >= NN) return;

    const int c0   = lane * VW;
    const int hl   = c0 / D;
    const int loff = lane * (2 * VW);

    float bv[VW];
    #pragma unroll
    for (int j = 0; j < VW; j++) bv[j] = bias[c0 + j];

    int bs0[2], bs1[2];

    // stage first (up to 32) edges of `node` into buffer `buf`
    auto prep = [&](int node, int buf) {
        const int s0 = g_rowptr[node];
        const int s1 = g_rowptr[node + 1];
        bs0[buf] = s0;
        bs1[buf] = s1;
        const int n = min(32, s1 - s0);
        if (lane < n) {
            const int idx = g_csrc[s0 + lane];
            sidx[warp][buf][lane] = idx;
            #pragma unroll
            for (int h = 0; h < H; h++) {
                float v0 = el0[idx * H + h] + er0[node * H + h];
                float v1 = el1[idx * H + h] + er1[node * H + h];
                v0 = (v0 > 0.f) ? v0 : 0.2f * v0;
                v1 = (v1 > 0.f) ? v1 : 0.2f * v1;
                swgt[warp][buf][lane * 2 * H + h]     = __expf(v0);
                swgt[warp][buf][lane * 2 * H + H + h] = __expf(v1);
            }
        }
    };

    prep(nbase, 0);
    __syncwarp();

    #pragma unroll
    for (int i = 0; i < NPW; i++) {
        const int cb   = i & 1;
        const int node = nbase + i;
        // issue next node's prep loads before streaming this node
        if (i + 1 < NPW) prep(node + 1, 1 - cb);

        const int s0 = bs0[cb];
        const int s1 = bs1[cb];

        float acc0[VW], acc1[VW];
        #pragma unroll
        for (int j = 0; j < VW; j++) { acc0[j] = 0.f; acc1[j] = 0.f; }
        float sum0 = 0.f, sum1 = 0.f;

        // ---- stream staged chunk 0 ----
        const int n0 = min(32, s1 - s0);
        #pragma unroll 4
        for (int j = 0; j < n0; j++) {
            const int sj = sidx[warp][cb][j];
            const float wj0 = swgt[warp][cb][j * 2 * H + hl];
            const float wj1 = swgt[warp][cb][j * 2 * H + H + hl];
            sum0 += wj0;
            sum1 += wj1;
            const __half* pA = hbase + (size_t)sj * (2 * HD) + loff;
            if constexpr (VW == 4) {
                uint4 u = *reinterpret_cast<const uint4*>(pA);
                float2 a = h2f(u.x), b = h2f(u.y);   // batch0
                float2 c = h2f(u.z), d = h2f(u.w);   // batch1
                acc0[0] = fmaf(wj0, a.x, acc0[0]);
                acc0[1] = fmaf(wj0, a.y, acc0[1]);
                acc0[2] = fmaf(wj0, b.x, acc0[2]);
                acc0[3] = fmaf(wj0, b.y, acc0[3]);
                acc1[0] = fmaf(wj1, c.x, acc1[0]);
                acc1[1] = fmaf(wj1, c.y, acc1[1]);
                acc1[2] = fmaf(wj1, d.x, acc1[2]);
                acc1[3] = fmaf(wj1, d.y, acc1[3]);
            } else {
                uint2 u = *reinterpret_cast<const uint2*>(pA);
                float2 a = h2f(u.x);                  // batch0
                float2 c = h2f(u.y);                  // batch1
                acc0[0] = fmaf(wj0, a.x, acc0[0]);
                acc0[1] = fmaf(wj0, a.y, acc0[1]);
                acc1[0] = fmaf(wj1, c.x, acc1[0]);
                acc1[1] = fmaf(wj1, c.y, acc1[1]);
            }
        }

        // ---- rare tail chunks (degree > 32): inline prep into buffer cb ----
        for (int p = s0 + 32; p < s1; p += 32) {
            __syncwarp();
            const int n = min(32, s1 - p);
            if (lane < n) {
                const int idx = g_csrc[p + lane];
                sidx[warp][cb][lane] = idx;
                #pragma unroll
                for (int h = 0; h < H; h++) {
                    float v0 = el0[idx * H + h] + er0[node * H + h];
                    float v1 = el1[idx * H + h] + er1[node * H + h];
                    v0 = (v0 > 0.f) ? v0 : 0.2f * v0;
                    v1 = (v1 > 0.f) ? v1 : 0.2f * v1;
                    swgt[warp][cb][lane * 2 * H + h]     = __expf(v0);
                    swgt[warp][cb][lane * 2 * H + H + h] = __expf(v1);
                }
            }
            __syncwarp();
            #pragma unroll 4
            for (int j = 0; j < n; j++) {
                const int sj = sidx[warp][cb][j];
                const float wj0 = swgt[warp][cb][j * 2 * H + hl];
                const float wj1 = swgt[warp][cb][j * 2 * H + H + hl];
                sum0 += wj0;
                sum1 += wj1;
                const __half* pA = hbase + (size_t)sj * (2 * HD) + loff;
                if constexpr (VW == 4) {
                    uint4 u = *reinterpret_cast<const uint4*>(pA);
                    float2 a = h2f(u.x), b = h2f(u.y);
                    float2 c = h2f(u.z), d = h2f(u.w);
                    acc0[0] = fmaf(wj0, a.x, acc0[0]);
                    acc0[1] = fmaf(wj0, a.y, acc0[1]);
                    acc0[2] = fmaf(wj0, b.x, acc0[2]);
                    acc0[3] = fmaf(wj0, b.y, acc0[3]);
                    acc1[0] = fmaf(wj1, c.x, acc1[0]);
                    acc1[1] = fmaf(wj1, c.y, acc1[1]);
                    acc1[2] = fmaf(wj1, d.x, acc1[2]);
                    acc1[3] = fmaf(wj1, d.y, acc1[3]);
                } else {
                    uint2 u = *reinterpret_cast<const uint2*>(pA);
                    float2 a = h2f(u.x);
                    float2 c = h2f(u.y);
                    acc0[0] = fmaf(wj0, a.x, acc0[0]);
                    acc0[1] = fmaf(wj0, a.y, acc0[1]);
                    acc1[0] = fmaf(wj1, c.x, acc1[0]);
                    acc1[1] = fmaf(wj1, c.y, acc1[1]);
                }
            }
        }

        // ---- epilogue for this node ----
        float out0[VW], out1[VW];
        if (s1 > s0) {
            const float i0 = 1.f / sum0;
            const float i1 = 1.f / sum1;
            #pragma unroll
            for (int j = 0; j < VW; j++) {
                out0[j] = fmaf(acc0[j], i0, bv[j]);
                out1[j] = fmaf(acc1[j], i1, bv[j]);
            }
        } else {
            #pragma unroll
            for (int j = 0; j < VW; j++) { out0[j] = bv[j]; out1[j] = bv[j]; }
        }
        if (RELU) {
            #pragma unroll
            for (int j = 0; j < VW; j++) {
                out0[j] = fmaxf(out0[j], 0.f);
                out1[j] = fmaxf(out1[j], 0.f);
            }
        }

        if constexpr (sizeof(OT) == 2) {
            if constexpr (VW == 4) {
                union { __half2 h[2]; uint2 u; } cv0, cv1;
                cv0.h[0] = __floats2half2_rn(out0[0], out0[1]);
                cv0.h[1] = __floats2half2_rn(out0[2], out0[3]);
                cv1.h[0] = __floats2half2_rn(out1[0], out1[1]);
                cv1.h[1] = __floats2half2_rn(out1[2], out1[3]);
                *reinterpret_cast<uint2*>(o0 + (size_t)node * HD + c0) = cv0.u;
                *reinterpret_cast<uint2*>(o1 + (size_t)node * HD + c0) = cv1.u;
            } else {
                __half2 v0 = __floats2half2_rn(out0[0], out0[1]);
                __half2 v1 = __floats2half2_rn(out1[0], out1[1]);
                *reinterpret_cast<unsigned*>(o0 + (size_t)node * HD + c0) =
                    *reinterpret_cast<unsigned*>(&v0);
                *reinterpret_cast<unsigned*>(o1 + (size_t)node * HD + c0) =
                    *reinterpret_cast<unsigned*>(&v1);
            }
        } else {
            if constexpr (VW == 4) {
                *reinterpret_cast<float4*>(o0 + (size_t)node * HD + c0) =
                    make_float4(out0[0], out0[1], out0[2], out0[3]);
                *reinterpret_cast<float4*>(o1 + (size_t)node * HD + c0) =
                    make_float4(out1[0], out1[1], out1[2], out1[3]);
            } else {
                *reinterpret_cast<float2*>(o0 + (size_t)node * HD + c0) =
                    make_float2(out0[0], out0[1]);
                *reinterpret_cast<float2*>(o1 + (size_t)node * HD + c0) =
                    make_float2(out1[0], out1[1]);
            }
        }

        __syncwarp();   // ensure next buffer's prep (issued above) is visible
    }
}

// ---------------- launcher ----------------
extern "C" void kernel_launch(void* const* d_in, const int* in_sizes, int n_in,
                              void* d_out, int out_size)
{
    const float* input = (const float*)d_in[0];
    const int*   src   = (const int*)  d_in[1];
    const int*   dst   = (const int*)  d_in[2];
    const float* W1    = (const float*)d_in[3];
    const float* al1   = (const float*)d_in[4];
    const float* ar1   = (const float*)d_in[5];
    const float* b1    = (const float*)d_in[6];
    const float* W2    = (const float*)d_in[7];
    const float* al2   = (const float*)d_in[8];
    const float* ar2   = (const float*)d_in[9];
    const float* b2    = (const float*)d_in[10];
    const float* W3    = (const float*)d_in[11];
    const float* al3   = (const float*)d_in[12];
    const float* ar3   = (const float*)d_in[13];
    const float* b3    = (const float*)d_in[14];
    float* out = (float*)d_out;

    void *ph, *px, *pw, *pel, *per;
    cudaGetSymbolAddress(&ph,  g_h);
    cudaGetSymbolAddress(&px,  g_x16);
    cudaGetSymbolAddress(&pw,  g_wh);
    cudaGetSymbolAddress(&pel, g_el);
    cudaGetSymbolAddress(&per, g_er);
    __half* hbuf = (__half*)ph;
    __half* x16  = (__half*)px;
    __half* wh   = (__half*)pw;
    float*  elb  = (float*)pel;
    float*  erb  = (float*)per;

    // fused prep (convert + zero) + CSR build
    prep_kernel<<<(BB * NN * DIN / 4 + 255) / 256, 256>>>(input, W1, W2, W3);
    hist_kernel<<<(EE + 255) / 256, 256>>>(dst);
    scan_kernel<<<1, 1024>>>();
    scatter_kernel<<<(EE + 255) / 256, 256>>>(src, dst);

    dim3 ggrid((NN + 63) / 64, BB);
    const int agrid = ((NN / 4) * 32 + 255) / 256;   // 4 nodes per warp

    // Layer 1: GATConv(64 -> 2 heads x 64)
    mma_gemm_att<64, 128, 2><<<ggrid, 128>>>(x16, wh, al1, ar1, hbuf, elb, erb);
    aggregate_kernel<128, 2, false, __half><<<agrid, 256>>>(hbuf, elb, erb, b1, x16, (size_t)NN * 128);

    // Layer 2: GATConv(128 -> 128, 1 head), ReLU
    mma_gemm_att<128, 128, 1><<<ggrid, 128>>>(x16, wh + 8192, al2, ar2, hbuf, elb, erb);
    aggregate_kernel<128, 1, true, __half><<<agrid, 256>>>(hbuf, elb, erb, b2, x16, (size_t)NN * 128);

    // Layer 3: GATConv(128 -> 64, 1 head)
    mma_gemm_att<128, 64, 1><<<ggrid, 128>>>(x16, wh + 24576, al3, ar3, hbuf, elb, erb);
    aggregate_kernel<64, 1, false, float><<<agrid, 256>>>(hbuf, elb, erb, b3, out, (size_t)NN * DOUTC);
}

// round 17
// speedup vs baseline: 1.1790x; 1.0526x over previous
#include <cuda_runtime.h>
#include <cuda_fp16.h>
#include <math.h>

// Problem constants
#define NN    50000
#define EE    800000
#define DIN   64
#define HIDD  128
#define DOUTC 64
#define BB    2

// ---------------- scratch (static device globals; no allocation) ----------------
// g_h layout is BATCH-INTERLEAVED per node: 32 chunks of 2*VW halves:
// [b0 feats VW*j..][b1 feats VW*j..]
__device__ __half g_h  [BB * NN * 128];  // projected features (interleaved gather table)
__device__ __half g_x16[BB * NN * 128];  // fp16 GEMM input (converted input / fp16 y)
__device__ __half g_wh [32768];          // W1(8192) | W2(16384) | W3(8192) fp16
__device__ float  g_el [BB * NN * 2];    // per-node attention left  (max 2 heads)
__device__ float  g_er [BB * NN * 2];    // per-node attention right
__device__ int    g_rowptr[NN + 1];      // CSR by dst
__device__ int    g_cursor[NN];          // degree / scatter cursor
__device__ int    g_csrc[EE];            // src per CSR slot

__device__ __forceinline__ unsigned smem_u32(const void* p) {
    return (unsigned)__cvta_generic_to_shared(p);
}

__device__ __forceinline__ float2 h2f(unsigned u) {
    return __half22float2(*reinterpret_cast<const __half2*>(&u));
}

// ---------------- fused prep: convert x + W to fp16, zero degree counters ----
__global__ void prep_kernel(const float* __restrict__ in,
                            const float* __restrict__ W1,
                            const float* __restrict__ W2,
                            const float* __restrict__ W3) {
    int i = blockIdx.x * blockDim.x + threadIdx.x;
    if (i < BB * NN * DIN / 4) {
        float4 v = reinterpret_cast<const float4*>(in)[i];
        union { __half2 h[2]; uint2 u; } cv;
        cv.h[0] = __floats2half2_rn(v.x, v.y);
        cv.h[1] = __floats2half2_rn(v.z, v.w);
        reinterpret_cast<uint2*>(g_x16)[i] = cv.u;
    }
    if (i < 32768) {
        if (i < 8192)       g_wh[i] = __float2half_rn(W1[i]);
        else if (i < 24576) g_wh[i] = __float2half_rn(W2[i - 8192]);
        else                g_wh[i] = __float2half_rn(W3[i - 24576]);
    }
    if (i < NN) g_cursor[i] = 0;
}

// ---------------- CSR build ----------------
__global__ void hist_kernel(const int* __restrict__ dst) {
    int e = blockIdx.x * blockDim.x + threadIdx.x;
    if (e < EE) atomicAdd(&g_cursor[dst[e]], 1);
}

__global__ void scan_kernel() {
    __shared__ int ss[1024];
    const int t  = threadIdx.x;
    const int CH = (NN + 1023) / 1024;
    const int b  = t * CH;
    const int e  = min(b + CH, NN);
    int s = 0;
    for (int i = b; i < e; i++) s += g_cursor[i];
    ss[t] = s;
    __syncthreads();
    for (int off = 1; off < 1024; off <<= 1) {
        int v = (t >= off) ? ss[t - off] : 0;
        __syncthreads();
        ss[t] += v;
        __syncthreads();
    }
    int run = (t == 0) ? 0 : ss[t - 1];
    for (int i = b; i < e; i++) {
        int d = g_cursor[i];
        g_rowptr[i] = run;
        g_cursor[i] = run;
        run += d;
    }
    if (t == 1023) g_rowptr[NN] = ss[1023];
}

__global__ void scatter_kernel(const int* __restrict__ src, const int* __restrict__ dst) {
    int e = blockIdx.x * blockDim.x + threadIdx.x;
    if (e < EE) {
        int p = atomicAdd(&g_cursor[dst[e]], 1);
        g_csrc[p] = src[e];
    }
}

// ---------------- HMMA (mma.sync m16n8k16) GEMM + attention epilogue ----------
// SINGLE-SHOT tiles: the full K-depth x and W tiles are loaded into dynamic
// smem with ONE sync (front-batched LDGs, high MLP), then mma straight
// through — no mid-kernel serial load phase.
template <int K, int HD, int H>
__global__ __launch_bounds__(128) void mma_gemm_att(
    const __half* __restrict__ xbase,
    const __half* __restrict__ Wh,
    const float* __restrict__ al, const float* __restrict__ ar,
    __half* __restrict__ hbase, float* __restrict__ elbase, float* __restrict__ erbase)
{
    constexpr int PX = K + 8;
    constexpr int PW = HD + 8;
    constexpr int NT = HD / 8;
    constexpr int D  = HD / H;
    constexpr int VW = HD / 32;

    extern __shared__ __align__(16) char smemraw[];
    __half* xs  = reinterpret_cast<__half*>(smemraw);
    __half* ws  = xs + 64 * PX;
    float*  sal = reinterpret_cast<float*>(ws + K * PW);
    float*  sar = sal + HD;

    const int bb = blockIdx.y;
    const __half* x  = xbase + (size_t)bb * NN * K;
    float*        el = elbase + (size_t)bb * NN * H;
    float*        er = erbase + (size_t)bb * NN * H;

    const int tid  = threadIdx.x;
    const int warp = tid >> 5;
    const int lane = tid & 31;
    const int g    = lane >> 2;
    const int t    = lane & 3;
    const int row0 = blockIdx.x * 64;

    for (int i = tid; i < HD; i += 128) { sal[i] = al[i]; sar[i] = ar[i]; }

    // ---- load full x tile: 64 rows x K halves ----
    #pragma unroll
    for (int idx = tid; idx < 64 * (K / 8); idx += 128) {
        int r = idx / (K / 8), j = idx % (K / 8);
        int grow = min(row0 + r, NN - 1);
        *reinterpret_cast<uint4*>(&xs[r * PX + j * 8]) =
            *reinterpret_cast<const uint4*>(&x[(size_t)grow * K + j * 8]);
    }
    // ---- load full W tile: K rows x HD halves ----
    #pragma unroll
    for (int idx = tid; idx < K * (HD / 8); idx += 128) {
        int r = idx / (HD / 8), j = idx % (HD / 8);
        *reinterpret_cast<uint4*>(&ws[r * PW + j * 8]) =
            *reinterpret_cast<const uint4*>(&Wh[(size_t)r * HD + j * 8]);
    }
    __syncthreads();

    float C[NT][4];
    #pragma unroll
    for (int j = 0; j < NT; j++)
        #pragma unroll
        for (int c = 0; c < 4; c++) C[j][c] = 0.f;

    #pragma unroll
    for (int kk = 0; kk < K; kk += 16) {
        unsigned a0, a1, a2, a3;
        {
            int i8  = lane & 7;
            int sel = lane >> 3;
            int arow = warp * 16 + i8 + (sel & 1) * 8;
            int akk  = kk + (sel >> 1) * 8;
            unsigned addr = smem_u32(&xs[arow * PX + akk]);
            asm volatile("ldmatrix.sync.aligned.m8n8.x4.shared.b16 {%0,%1,%2,%3}, [%4];"
                         : "=r"(a0), "=r"(a1), "=r"(a2), "=r"(a3) : "r"(addr));
        }
        #pragma unroll
        for (int j = 0; j < NT; j++) {
            unsigned b0, b1;
            int i8 = lane & 7;
            int s  = (lane >> 3) & 1;
            unsigned baddr = smem_u32(&ws[(kk + s * 8 + i8) * PW + j * 8]);
            asm volatile("ldmatrix.sync.aligned.m8n8.x2.trans.shared.b16 {%0,%1}, [%2];"
                         : "=r"(b0), "=r"(b1) : "r"(baddr));
            asm volatile("mma.sync.aligned.m16n8k16.row.col.f32.f16.f16.f32 "
                         "{%0,%1,%2,%3}, {%4,%5,%6,%7}, {%8,%9}, {%0,%1,%2,%3};"
                         : "+f"(C[j][0]), "+f"(C[j][1]), "+f"(C[j][2]), "+f"(C[j][3])
                         : "r"(a0), "r"(a1), "r"(a2), "r"(a3), "r"(b0), "r"(b1));
        }
    }

    const int row_a = row0 + warp * 16 + g;
    const int row_b = row_a + 8;

    float pelA[H], perA[H], pelB[H], perB[H];
    #pragma unroll
    for (int h = 0; h < H; h++) { pelA[h] = 0.f; perA[h] = 0.f; pelB[h] = 0.f; perB[h] = 0.f; }

    #pragma unroll
    for (int j = 0; j < NT; j++) {
        const int cc = j * 8 + 2 * t;
        const int hh = (j * 8) / D;
        const float a0v = sal[cc], a1v = sal[cc + 1];
        const float r0v = sar[cc], r1v = sar[cc + 1];
        pelA[hh] = fmaf(C[j][0], a0v, fmaf(C[j][1], a1v, pelA[hh]));
        perA[hh] = fmaf(C[j][0], r0v, fmaf(C[j][1], r1v, perA[hh]));
        pelB[hh] = fmaf(C[j][2], a0v, fmaf(C[j][3], a1v, pelB[hh]));
        perB[hh] = fmaf(C[j][2], r0v, fmaf(C[j][3], r1v, perB[hh]));
        const int ioff = (cc / VW) * (2 * VW) + bb * VW + (cc % VW);
        if (row_a < NN) {
            __half2 hv = __floats2half2_rn(C[j][0], C[j][1]);
            *reinterpret_cast<unsigned*>(&hbase[(size_t)row_a * (2 * HD) + ioff]) =
                *reinterpret_cast<unsigned*>(&hv);
        }
        if (row_b < NN) {
            __half2 hv = __floats2half2_rn(C[j][2], C[j][3]);
            *reinterpret_cast<unsigned*>(&hbase[(size_t)row_b * (2 * HD) + ioff]) =
                *reinterpret_cast<unsigned*>(&hv);
        }
    }

    #pragma unroll
    for (int h = 0; h < H; h++) {
        pelA[h] += __shfl_xor_sync(0xffffffffu, pelA[h], 1);
        pelA[h] += __shfl_xor_sync(0xffffffffu, pelA[h], 2);
        perA[h] += __shfl_xor_sync(0xffffffffu, perA[h], 1);
        perA[h] += __shfl_xor_sync(0xffffffffu, perA[h], 2);
        pelB[h] += __shfl_xor_sync(0xffffffffu, pelB[h], 1);
        pelB[h] += __shfl_xor_sync(0xffffffffu, pelB[h], 2);
        perB[h] += __shfl_xor_sync(0xffffffffu, perB[h], 1);
        perB[h] += __shfl_xor_sync(0xffffffffu, perB[h], 2);
    }
    if (t == 0) {
        #pragma unroll
        for (int h = 0; h < H; h++) {
            if (row_a < NN) { el[row_a * H + h] = pelA[h]; er[row_a * H + h] = perA[h]; }
            if (row_b < NN) { el[row_b * H + h] = pelB[h]; er[row_b * H + h] = perB[h]; }
        }
    }
}

// ---------------- node-pipelined warp-cooperative aggregation ----------------
// Each warp owns 4 consecutive nodes with double-buffered staging: while
// streaming node i's h-gathers, node i+1's prep loads (rowptr/csrc/el/exp)
// are already in flight into the other buffer.
template <int HD, int H, bool RELU, typename OT>
__global__ __launch_bounds__(256) void aggregate_kernel(
    const __half* __restrict__ hbase, const float* __restrict__ elbase,
    const float* __restrict__ erbase, const float* __restrict__ bias,
    OT* __restrict__ outbase, size_t outstride)
{
    constexpr int VW  = HD / 32;
    constexpr int D   = HD / H;
    constexpr int NPW = 4;          // nodes per warp (NN % 4 == 0)

    __shared__ int   sidx[8][2][32];
    __shared__ float swgt[8][2][32 * 2 * H];

    const float*  el0 = elbase;
    const float*  el1 = elbase + (size_t)NN * H;
    const float*  er0 = erbase;
    const float*  er1 = erbase + (size_t)NN * H;
    OT*           o0  = outbase;
    OT*           o1  = outbase + outstride;

    const int warp  = threadIdx.x >> 5;
    const int lane  = threadIdx.x & 31;
    const int gw    = (blockIdx.x * blockDim.x + threadIdx.x) >> 5;
    const int nbase = gw * NPW;
    if (nbase >= NN) return;

    const int c0   = lane * VW;
    const int hl   = c0 / D;
    const int loff = lane * (2 * VW);

    float bv[VW];
    #pragma unroll
    for (int j = 0; j < VW; j++) bv[j] = bias[c0 + j];

    int bs0[2], bs1[2];

    auto prep = [&](int node, int buf) {
        const int s0 = g_rowptr[node];
        const int s1 = g_rowptr[node + 1];
        bs0[buf] = s0;
        bs1[buf] = s1;
        const int n = min(32, s1 - s0);
        if (lane < n) {
            const int idx = g_csrc[s0 + lane];
            sidx[warp][buf][lane] = idx;
            #pragma unroll
            for (int h = 0; h < H; h++) {
                float v0 = el0[idx * H + h] + er0[node * H + h];
                float v1 = el1[idx * H + h] + er1[node * H + h];
                v0 = (v0 > 0.f) ? v0 : 0.2f * v0;
                v1 = (v1 > 0.f) ? v1 : 0.2f * v1;
                swgt[warp][buf][lane * 2 * H + h]     = __expf(v0);
                swgt[warp][buf][lane * 2 * H + H + h] = __expf(v1);
            }
        }
    };

    prep(nbase, 0);
    __syncwarp();

    #pragma unroll
    for (int i = 0; i < NPW; i++) {
        const int cb   = i & 1;
        const int node = nbase + i;
        if (i + 1 < NPW) prep(node + 1, 1 - cb);

        const int s0 = bs0[cb];
        const int s1 = bs1[cb];

        float acc0[VW], acc1[VW];
        #pragma unroll
        for (int j = 0; j < VW; j++) { acc0[j] = 0.f; acc1[j] = 0.f; }
        float sum0 = 0.f, sum1 = 0.f;

        const int n0 = min(32, s1 - s0);
        #pragma unroll 4
        for (int j = 0; j < n0; j++) {
            const int sj = sidx[warp][cb][j];
            const float wj0 = swgt[warp][cb][j * 2 * H + hl];
            const float wj1 = swgt[warp][cb][j * 2 * H + H + hl];
            sum0 += wj0;
            sum1 += wj1;
            const __half* pA = hbase + (size_t)sj * (2 * HD) + loff;
            if constexpr (VW == 4) {
                uint4 u = *reinterpret_cast<const uint4*>(pA);
                float2 a = h2f(u.x), b = h2f(u.y);   // batch0
                float2 c = h2f(u.z), d = h2f(u.w);   // batch1
                acc0[0] = fmaf(wj0, a.x, acc0[0]);
                acc0[1] = fmaf(wj0, a.y, acc0[1]);
                acc0[2] = fmaf(wj0, b.x, acc0[2]);
                acc0[3] = fmaf(wj0, b.y, acc0[3]);
                acc1[0] = fmaf(wj1, c.x, acc1[0]);
                acc1[1] = fmaf(wj1, c.y, acc1[1]);
                acc1[2] = fmaf(wj1, d.x, acc1[2]);
                acc1[3] = fmaf(wj1, d.y, acc1[3]);
            } else {
                uint2 u = *reinterpret_cast<const uint2*>(pA);
                float2 a = h2f(u.x);                  // batch0
                float2 c = h2f(u.y);                  // batch1
                acc0[0] = fmaf(wj0, a.x, acc0[0]);
                acc0[1] = fmaf(wj0, a.y, acc0[1]);
                acc1[0] = fmaf(wj1, c.x, acc1[0]);
                acc1[1] = fmaf(wj1, c.y, acc1[1]);
            }
        }

        // rare tail chunks (degree > 32): inline prep into buffer cb
        for (int p = s0 + 32; p < s1; p += 32) {
            __syncwarp();
            const int n = min(32, s1 - p);
            if (lane < n) {
                const int idx = g_csrc[p + lane];
                sidx[warp][cb][lane] = idx;
                #pragma unroll
                for (int h = 0; h < H; h++) {
                    float v0 = el0[idx * H + h] + er0[node * H + h];
                    float v1 = el1[idx * H + h] + er1[node * H + h];
                    v0 = (v0 > 0.f) ? v0 : 0.2f * v0;
                    v1 = (v1 > 0.f) ? v1 : 0.2f * v1;
                    swgt[warp][cb][lane * 2 * H + h]     = __expf(v0);
                    swgt[warp][cb][lane * 2 * H + H + h] = __expf(v1);
                }
            }
            __syncwarp();
            #pragma unroll 4
            for (int j = 0; j < n; j++) {
                const int sj = sidx[warp][cb][j];
                const float wj0 = swgt[warp][cb][j * 2 * H + hl];
                const float wj1 = swgt[warp][cb][j * 2 * H + H + hl];
                sum0 += wj0;
                sum1 += wj1;
                const __half* pA = hbase + (size_t)sj * (2 * HD) + loff;
                if constexpr (VW == 4) {
                    uint4 u = *reinterpret_cast<const uint4*>(pA);
                    float2 a = h2f(u.x), b = h2f(u.y);
                    float2 c = h2f(u.z), d = h2f(u.w);
                    acc0[0] = fmaf(wj0, a.x, acc0[0]);
                    acc0[1] = fmaf(wj0, a.y, acc0[1]);
                    acc0[2] = fmaf(wj0, b.x, acc0[2]);
                    acc0[3] = fmaf(wj0, b.y, acc0[3]);
                    acc1[0] = fmaf(wj1, c.x, acc1[0]);
                    acc1[1] = fmaf(wj1, c.y, acc1[1]);
                    acc1[2] = fmaf(wj1, d.x, acc1[2]);
                    acc1[3] = fmaf(wj1, d.y, acc1[3]);
                } else {
                    uint2 u = *reinterpret_cast<const uint2*>(pA);
                    float2 a = h2f(u.x);
                    float2 c = h2f(u.y);
                    acc0[0] = fmaf(wj0, a.x, acc0[0]);
                    acc0[1] = fmaf(wj0, a.y, acc0[1]);
                    acc1[0] = fmaf(wj1, c.x, acc1[0]);
                    acc1[1] = fmaf(wj1, c.y, acc1[1]);
                }
            }
        }

        float out0[VW], out1[VW];
        if (s1 > s0) {
            const float i0 = 1.f / sum0;
            const float i1 = 1.f / sum1;
            #pragma unroll
            for (int j = 0; j < VW; j++) {
                out0[j] = fmaf(acc0[j], i0, bv[j]);
                out1[j] = fmaf(acc1[j], i1, bv[j]);
            }
        } else {
            #pragma unroll
            for (int j = 0; j < VW; j++) { out0[j] = bv[j]; out1[j] = bv[j]; }
        }
        if (RELU) {
            #pragma unroll
            for (int j = 0; j < VW; j++) {
                out0[j] = fmaxf(out0[j], 0.f);
                out1[j] = fmaxf(out1[j], 0.f);
            }
        }

        if constexpr (sizeof(OT) == 2) {
            if constexpr (VW == 4) {
                union { __half2 h[2]; uint2 u; } cv0, cv1;
                cv0.h[0] = __floats2half2_rn(out0[0], out0[1]);
                cv0.h[1] = __floats2half2_rn(out0[2], out0[3]);
                cv1.h[0] = __floats2half2_rn(out1[0], out1[1]);
                cv1.h[1] = __floats2half2_rn(out1[2], out1[3]);
                *reinterpret_cast<uint2*>(o0 + (size_t)node * HD + c0) = cv0.u;
                *reinterpret_cast<uint2*>(o1 + (size_t)node * HD + c0) = cv1.u;
            } else {
                __half2 v0 = __floats2half2_rn(out0[0], out0[1]);
                __half2 v1 = __floats2half2_rn(out1[0], out1[1]);
                *reinterpret_cast<unsigned*>(o0 + (size_t)node * HD + c0) =
                    *reinterpret_cast<unsigned*>(&v0);
                *reinterpret_cast<unsigned*>(o1 + (size_t)node * HD + c0) =
                    *reinterpret_cast<unsigned*>(&v1);
            }
        } else {
            if constexpr (VW == 4) {
                *reinterpret_cast<float4*>(o0 + (size_t)node * HD + c0) =
                    make_float4(out0[0], out0[1], out0[2], out0[3]);
                *reinterpret_cast<float4*>(o1 + (size_t)node * HD + c0) =
                    make_float4(out1[0], out1[1], out1[2], out1[3]);
            } else {
                *reinterpret_cast<float2*>(o0 + (size_t)node * HD + c0) =
                    make_float2(out0[0], out0[1]);
                *reinterpret_cast<float2*>(o1 + (size_t)node * HD + c0) =
                    make_float2(out1[0], out1[1]);
            }
        }

        __syncwarp();
    }
}

// ---------------- launcher ----------------
static inline int gemm_smem_bytes(int K, int HD) {
    return 64 * (K + 8) * 2 + K * (HD + 8) * 2 + 2 * HD * 4;
}

extern "C" void kernel_launch(void* const* d_in, const int* in_sizes, int n_in,
                              void* d_out, int out_size)
{
    const float* input = (const float*)d_in[0];
    const int*   src   = (const int*)  d_in[1];
    const int*   dst   = (const int*)  d_in[2];
    const float* W1    = (const float*)d_in[3];
    const float* al1   = (const float*)d_in[4];
    const float* ar1   = (const float*)d_in[5];
    const float* b1    = (const float*)d_in[6];
    const float* W2    = (const float*)d_in[7];
    const float* al2   = (const float*)d_in[8];
    const float* ar2   = (const float*)d_in[9];
    const float* b2    = (const float*)d_in[10];
    const float* W3    = (const float*)d_in[11];
    const float* al3   = (const float*)d_in[12];
    const float* ar3   = (const float*)d_in[13];
    const float* b3    = (const float*)d_in[14];
    float* out = (float*)d_out;

    void *ph, *px, *pw, *pel, *per;
    cudaGetSymbolAddress(&ph,  g_h);
    cudaGetSymbolAddress(&px,  g_x16);
    cudaGetSymbolAddress(&pw,  g_wh);
    cudaGetSymbolAddress(&pel, g_el);
    cudaGetSymbolAddress(&per, g_er);
    __half* hbuf = (__half*)ph;
    __half* x16  = (__half*)px;
    __half* wh   = (__half*)pw;
    float*  elb  = (float*)pel;
    float*  erb  = (float*)per;

    const int sm1 = gemm_smem_bytes(64, 128);
    const int sm2 = gemm_smem_bytes(128, 128);
    const int sm3 = gemm_smem_bytes(128, 64);
    cudaFuncSetAttribute(mma_gemm_att<64, 128, 2>,
                         cudaFuncAttributeMaxDynamicSharedMemorySize, sm1);
    cudaFuncSetAttribute(mma_gemm_att<128, 128, 1>,
                         cudaFuncAttributeMaxDynamicSharedMemorySize, sm2);
    cudaFuncSetAttribute(mma_gemm_att<128, 64, 1>,
                         cudaFuncAttributeMaxDynamicSharedMemorySize, sm3);

    // fused prep (convert + zero) + CSR build
    prep_kernel<<<(BB * NN * DIN / 4 + 255) / 256, 256>>>(input, W1, W2, W3);
    hist_kernel<<<(EE + 255) / 256, 256>>>(dst);
    scan_kernel<<<1, 1024>>>();
    scatter_kernel<<<(EE + 255) / 256, 256>>>(src, dst);

    dim3 ggrid((NN + 63) / 64, BB);
    const int agrid = ((NN / 4) * 32 + 255) / 256;   // 4 nodes per warp

    // Layer 1: GATConv(64 -> 2 heads x 64)
    mma_gemm_att<64, 128, 2><<<ggrid, 128, sm1>>>(x16, wh, al1, ar1, hbuf, elb, erb);
    aggregate_kernel<128, 2, false, __half><<<agrid, 256>>>(hbuf, elb, erb, b1, x16, (size_t)NN * 128);

    // Layer 2: GATConv(128 -> 128, 1 head), ReLU
    mma_gemm_att<128, 128, 1><<<ggrid, 128, sm2>>>(x16, wh + 8192, al2, ar2, hbuf, elb, erb);
    aggregate_kernel<128, 1, true, __half><<<agrid, 256>>>(hbuf, elb, erb, b2, x16, (size_t)NN * 128);

    // Layer 3: GATConv(128 -> 64, 1 head)
    mma_gemm_att<128, 64, 1><<<ggrid, 128, sm3>>>(x16, wh + 24576, al3, ar3, hbuf, elb, erb);
    aggregate_kernel<64, 1, false, float><<<agrid, 256>>>(hbuf, elb, erb, b3, out, (size_t)NN * DOUTC);
}